// round 2
// baseline (speedup 1.0000x reference)
#include <cuda_runtime.h>
#include <math.h>

// ---------------- problem constants ----------------
#define Vv    32000
#define Dd    768
#define NLl   2
#define Bb    2
#define Tt    1024
#define EDe   1536
#define NSn   16
#define KC    4
#define DTR   48
#define BT    (Bb*Tt)        // 2048
#define XZc   (2*EDe)        // 3072
#define DBCP  128            // padded dbc width (80 -> 128)

// ---------------- scratch (static device globals; no allocations) ----------------
__device__ __align__(16) float g_x    [BT*Dd];     // activations (layer in/out)
__device__ __align__(16) float g_xz   [BT*XZc];    // in_proj output (xin | z)
__device__ __align__(16) float g_xin  [BT*EDe];    // conv+silu output
__device__ __align__(16) float g_dbc  [BT*DBCP];   // x_proj output, padded to 128
__device__ __align__(16) float g_delta[BT*EDe];    // dt (raw then softplus)
__device__ __align__(16) float g_du   [BT*EDe];    // delta * xin
__device__ __align__(16) float g_y    [BT*EDe];    // gated scan output
__device__ __align__(16) float g_out  [BT*Dd];     // out_proj output (pre-LN)
__device__ __align__(16) float g_xpw  [DBCP*EDe];  // padded x_proj_w

// ---------------- embedding gather (float4) ----------------
__global__ void k_embed(const int* __restrict__ tok, const float* __restrict__ emb,
                        float* __restrict__ x)
{
    int i = blockIdx.x * blockDim.x + threadIdx.x;          // over BT * (Dd/4)
    if (i >= BT * (Dd/4)) return;
    int r  = i / (Dd/4);
    int c4 = i - r * (Dd/4);
    ((float4*)x)[i] = ((const float4*)(emb + (size_t)tok[r] * Dd))[c4];
}

// ---------------- generic NT GEMM: C[M,N] = A[M,K] * B[N,K]^T (+bias) ----------------
// BM=BN=128, BK=16, 256 threads, 8x8 per thread. Requires M,N %128==0, K %16==0,
// lda/ldb/ldc such that all float4 accesses are 16B aligned (true for all call sites).
__global__ void __launch_bounds__(256) k_gemm_nt(
    const float* __restrict__ A, int lda,
    const float* __restrict__ B, int ldb,
    const float* __restrict__ bias,
    float* __restrict__ C, int ldc, int Kd)
{
    __shared__ float As[16][128];
    __shared__ float Bs[16][128];

    const int tid = threadIdx.x;
    const int bm = blockIdx.y * 128, bn = blockIdx.x * 128;

    const int r0 = tid >> 2;            // 0..63
    const int kq = (tid & 3) << 2;      // 0,4,8,12

    const float* Ap0 = A + (size_t)(bm + r0)      * lda + kq;
    const float* Ap1 = A + (size_t)(bm + r0 + 64) * lda + kq;
    const float* Bp0 = B + (size_t)(bn + r0)      * ldb + kq;
    const float* Bp1 = B + (size_t)(bn + r0 + 64) * ldb + kq;

    const int tx = tid & 15, ty = tid >> 4;

    float acc[8][8];
#pragma unroll
    for (int i = 0; i < 8; i++)
#pragma unroll
        for (int j = 0; j < 8; j++) acc[i][j] = 0.f;

    float4 ra0 = *(const float4*)Ap0;
    float4 ra1 = *(const float4*)Ap1;
    float4 rb0 = *(const float4*)Bp0;
    float4 rb1 = *(const float4*)Bp1;

    const int ntiles = Kd >> 4;
    for (int kt = 0; kt < ntiles; kt++) {
        // store (transposed) current tile
        As[kq+0][r0]    = ra0.x; As[kq+1][r0]    = ra0.y; As[kq+2][r0]    = ra0.z; As[kq+3][r0]    = ra0.w;
        As[kq+0][r0+64] = ra1.x; As[kq+1][r0+64] = ra1.y; As[kq+2][r0+64] = ra1.z; As[kq+3][r0+64] = ra1.w;
        Bs[kq+0][r0]    = rb0.x; Bs[kq+1][r0]    = rb0.y; Bs[kq+2][r0]    = rb0.z; Bs[kq+3][r0]    = rb0.w;
        Bs[kq+0][r0+64] = rb1.x; Bs[kq+1][r0+64] = rb1.y; Bs[kq+2][r0+64] = rb1.z; Bs[kq+3][r0+64] = rb1.w;
        __syncthreads();

        if (kt + 1 < ntiles) {          // prefetch next tile into registers
            Ap0 += 16; Ap1 += 16; Bp0 += 16; Bp1 += 16;
            ra0 = *(const float4*)Ap0;
            ra1 = *(const float4*)Ap1;
            rb0 = *(const float4*)Bp0;
            rb1 = *(const float4*)Bp1;
        }

#pragma unroll
        for (int kk = 0; kk < 16; kk++) {
            float a[8], bb[8];
            *(float4*)(a)      = *(const float4*)&As[kk][ty*8];
            *(float4*)(a + 4)  = *(const float4*)&As[kk][ty*8 + 4];
            *(float4*)(bb)     = *(const float4*)&Bs[kk][tx*8];
            *(float4*)(bb + 4) = *(const float4*)&Bs[kk][tx*8 + 4];
#pragma unroll
            for (int i = 0; i < 8; i++)
#pragma unroll
                for (int j = 0; j < 8; j++)
                    acc[i][j] = fmaf(a[i], bb[j], acc[i][j]);
        }
        __syncthreads();
    }

    float bv[8];
#pragma unroll
    for (int j = 0; j < 8; j++) bv[j] = bias ? bias[bn + tx*8 + j] : 0.f;

#pragma unroll
    for (int i = 0; i < 8; i++) {
        size_t row = (size_t)(bm + ty*8 + i);
        float4 o0, o1;
        o0.x = acc[i][0] + bv[0]; o0.y = acc[i][1] + bv[1];
        o0.z = acc[i][2] + bv[2]; o0.w = acc[i][3] + bv[3];
        o1.x = acc[i][4] + bv[4]; o1.y = acc[i][5] + bv[5];
        o1.z = acc[i][6] + bv[6]; o1.w = acc[i][7] + bv[7];
        *(float4*)&C[row*ldc + bn + tx*8]     = o0;
        *(float4*)&C[row*ldc + bn + tx*8 + 4] = o1;
    }
}

// ---------------- causal depthwise conv (K=4) + bias + SiLU ----------------
__global__ void k_conv(const float* __restrict__ xz, const float* __restrict__ cw,
                       const float* __restrict__ cb, float* __restrict__ xin)
{
    int i = blockIdx.x * blockDim.x + threadIdx.x;
    if (i >= BT * EDe) return;
    int bt = i / EDe, e = i - bt * EDe;
    int b = bt >> 10, t = bt & (Tt - 1);
    float s = cb[e];
    const float* col = xz + (size_t)(b * Tt) * XZc + e;
#pragma unroll
    for (int j = 0; j < KC; j++) {
        int tt = t - (KC - 1) + j;
        if (tt >= 0) s = fmaf(cw[e*KC + j], col[(size_t)tt * XZc], s);
    }
    xin[i] = s / (1.f + __expf(-s));
}

// ---------------- pad x_proj_w (80 rows) into 128-row buffer ----------------
__global__ void k_pad(const float* __restrict__ xpw, float* __restrict__ dst)
{
    int i = blockIdx.x * blockDim.x + threadIdx.x;
    if (i >= DBCP * EDe) return;
    dst[i] = (i < (DTR + 2*NSn) * EDe) ? xpw[i] : 0.f;
}

// ---------------- delta = softplus(raw + dt_b); du = delta * xin ----------------
__global__ void k_ewdelta(const float* __restrict__ dtb)
{
    int i = blockIdx.x * blockDim.x + threadIdx.x;
    if (i >= BT * EDe) return;
    int e = i % EDe;
    float raw = g_delta[i] + dtb[e];
    float sp = (raw > 20.f) ? raw : log1pf(__expf(raw));
    g_delta[i] = sp;
    g_du[i]    = sp * g_xin[i];
}

// ---------------- selective scan: warp = 2 channels x 16 states ----------------
__global__ void k_scan(const float* __restrict__ a_log, const float* __restrict__ d_par)
{
    int gid  = blockIdx.x * blockDim.x + threadIdx.x;
    int warp = gid >> 5, lane = gid & 31;
    if (warp >= Bb * (EDe/2)) return;
    int b  = warp / (EDe/2);
    int ep = warp - b * (EDe/2);
    int e  = ep * 2 + (lane >> 4);
    int n  = lane & 15;

    float Ac = -__expf(a_log[e*NSn + n]);
    float dp = d_par[e];
    float h  = 0.f;
    size_t baseBT = (size_t)b * Tt;

    for (int t = 0; t < Tt; t++) {
        size_t bt = baseBT + t;
        float dv  = g_delta[bt*EDe + e];
        float duv = g_du   [bt*EDe + e];
        float Bv  = g_dbc  [bt*DBCP + DTR + n];
        float Cv  = g_dbc  [bt*DBCP + DTR + NSn + n];
        float dA  = __expf(dv * Ac);
        h = fmaf(dA, h, duv * Bv);
        float c = h * Cv;
        c += __shfl_xor_sync(0xffffffffu, c, 8);
        c += __shfl_xor_sync(0xffffffffu, c, 4);
        c += __shfl_xor_sync(0xffffffffu, c, 2);
        c += __shfl_xor_sync(0xffffffffu, c, 1);
        if (n == 0) {
            float xv = g_xin[bt*EDe + e];
            float zv = g_xz [bt*XZc + EDe + e];
            float gt = zv / (1.f + __expf(-zv));
            g_y[bt*EDe + e] = (c + dp * xv) * gt;
        }
    }
}

// ---------------- LayerNorm over D=768, writes into g_x ----------------
__global__ void k_ln(const float* __restrict__ w, const float* __restrict__ b)
{
    int row = blockIdx.x, tid = threadIdx.x;     // 256 threads
    const float* r = g_out + (size_t)row * Dd;
    float v0 = r[tid], v1 = r[tid+256], v2 = r[tid+512];
    float s  = v0 + v1 + v2;
    float sq = v0*v0 + v1*v1 + v2*v2;
#pragma unroll
    for (int o = 16; o; o >>= 1) {
        s  += __shfl_xor_sync(0xffffffffu, s,  o);
        sq += __shfl_xor_sync(0xffffffffu, sq, o);
    }
    __shared__ float ss[8], sqq[8];
    if ((tid & 31) == 0) { ss[tid>>5] = s; sqq[tid>>5] = sq; }
    __syncthreads();
    s = 0.f; sq = 0.f;
#pragma unroll
    for (int i = 0; i < 8; i++) { s += ss[i]; sq += sqq[i]; }
    float mu  = s * (1.f / Dd);
    float var = sq * (1.f / Dd) - mu * mu;
    float inv = rsqrtf(var + 1e-5f);
    float* o = g_x + (size_t)row * Dd;
    o[tid]     = (v0 - mu) * inv * w[tid]     + b[tid];
    o[tid+256] = (v1 - mu) * inv * w[tid+256] + b[tid+256];
    o[tid+512] = (v2 - mu) * inv * w[tid+512] + b[tid+512];
}

// ---------------- launch ----------------
extern "C" void kernel_launch(void* const* d_in, const int* in_sizes, int n_in,
                              void* d_out, int out_size)
{
    const int*   tokens = (const int*)  d_in[0];
    const float* embed  = (const float*)d_in[1];
    const float* in_w   = (const float*)d_in[2];
    const float* conv_w = (const float*)d_in[3];
    const float* conv_b = (const float*)d_in[4];
    const float* xp_w   = (const float*)d_in[5];
    const float* dt_w   = (const float*)d_in[6];
    const float* dt_b   = (const float*)d_in[7];
    const float* a_log  = (const float*)d_in[8];
    const float* d_par  = (const float*)d_in[9];
    const float* out_w  = (const float*)d_in[10];
    const float* ln_w   = (const float*)d_in[11];
    const float* ln_b   = (const float*)d_in[12];
    const float* head_w = (const float*)d_in[13];
    const float* head_b = (const float*)d_in[14];
    float* out = (float*)d_out;

    float *p_x, *p_xz, *p_xin, *p_dbc, *p_delta, *p_y, *p_out, *p_xpw;
    cudaGetSymbolAddress((void**)&p_x,     g_x);
    cudaGetSymbolAddress((void**)&p_xz,    g_xz);
    cudaGetSymbolAddress((void**)&p_xin,   g_xin);
    cudaGetSymbolAddress((void**)&p_dbc,   g_dbc);
    cudaGetSymbolAddress((void**)&p_delta, g_delta);
    cudaGetSymbolAddress((void**)&p_y,     g_y);
    cudaGetSymbolAddress((void**)&p_out,   g_out);
    cudaGetSymbolAddress((void**)&p_xpw,   g_xpw);

    // embed
    k_embed<<<(BT*(Dd/4) + 255)/256, 256>>>(tokens, embed, p_x);

    for (int l = 0; l < NLl; l++) {
        // in_proj: xz = x @ in_w^T   (M=2048, N=3072, K=768)
        k_gemm_nt<<<dim3(XZc/128, BT/128), 256>>>(
            p_x, Dd, in_w + (size_t)l*XZc*Dd, Dd, nullptr, p_xz, XZc, Dd);

        // conv + silu
        k_conv<<<(BT*EDe + 255)/256, 256>>>(p_xz, conv_w + (size_t)l*EDe*KC,
                                            conv_b + (size_t)l*EDe, p_xin);

        // pad x_proj_w and x_proj GEMM (M=2048, N=128, K=1536)
        k_pad<<<(DBCP*EDe + 255)/256, 256>>>(xp_w + (size_t)l*(DTR+2*NSn)*EDe, p_xpw);
        k_gemm_nt<<<dim3(1, BT/128), 256>>>(
            p_xin, EDe, p_xpw, EDe, nullptr, p_dbc, DBCP, EDe);

        // dt_proj GEMM (M=2048, N=1536, K=48) -> raw delta
        k_gemm_nt<<<dim3(EDe/128, BT/128), 256>>>(
            p_dbc, DBCP, dt_w + (size_t)l*EDe*DTR, DTR, nullptr, p_delta, EDe, DTR);

        // softplus + du
        k_ewdelta<<<(BT*EDe + 255)/256, 256>>>(dt_b + (size_t)l*EDe);

        // selective scan + D skip + gate
        k_scan<<<(Bb*(EDe/2)*32 + 255)/256, 256>>>(a_log + (size_t)l*EDe*NSn,
                                                   d_par + (size_t)l*EDe);

        // out_proj GEMM (M=2048, N=768, K=1536)
        k_gemm_nt<<<dim3(Dd/128, BT/128), 256>>>(
            p_y, EDe, out_w + (size_t)l*Dd*EDe, EDe, nullptr, p_out, Dd, EDe);

        // layernorm -> g_x
        k_ln<<<BT, 256>>>(ln_w + (size_t)l*Dd, ln_b + (size_t)l*Dd);
    }

    // head GEMM (M=2048, N=32000, K=768) + bias -> output
    k_gemm_nt<<<dim3(Vv/128, BT/128), 256>>>(
        p_x, Dd, head_w, Dd, head_b, out, Vv, Dd);

    (void)in_sizes; (void)n_in; (void)out_size;
}

// round 6
// speedup vs baseline: 2.3481x; 2.3481x over previous
#include <cuda_runtime.h>
#include <cuda_bf16.h>
#include <cstdint>
#include <math.h>

// ---------------- problem constants ----------------
#define Vv    32000
#define Dd    768
#define NLl   2
#define Bb    2
#define Tt    1024
#define EDe   1536
#define NSn   16
#define KC    4
#define DTR   48
#define BT    (Bb*Tt)        // 2048
#define XZc   (2*EDe)        // 3072
#define DBCP  128            // padded dbc width (80 -> 128)

// ---------------- scratch (static device globals; no allocations) ----------------
__device__ __align__(16) float g_x    [BT*Dd];
__device__ __align__(16) float g_xz   [BT*XZc];
__device__ __align__(16) float g_xin  [BT*EDe];
__device__ __align__(16) float g_dbc  [BT*DBCP];
__device__ __align__(16) float g_delta[BT*EDe];
__device__ __align__(16) float g_du   [BT*EDe];
__device__ __align__(16) float g_y    [BT*EDe];
__device__ __align__(16) float g_out  [BT*Dd];
__device__ __align__(16) float g_xpw  [DBCP*EDe];

__device__ __forceinline__ uint32_t smem_to_u32(const void* p) {
    uint32_t a;
    asm("{ .reg .u64 t; cvta.to.shared.u64 t, %1; cvt.u32.u64 %0, t; }" : "=r"(a) : "l"(p));
    return a;
}

// fp32 x4 -> (hi, lo) bf16 split, stored as 2x b32 into hi/lo smem tiles
// smem row stride = 80 bytes (40 bf16) -> ldmatrix & stores conflict-free mod 128B
__device__ __forceinline__ void cvt_store(uint32_t hi_base, uint32_t lo_base,
                                          int row, int col, float4 v)
{
    __nv_bfloat16 hx = __float2bfloat16(v.x);
    __nv_bfloat16 hy = __float2bfloat16(v.y);
    __nv_bfloat16 hz = __float2bfloat16(v.z);
    __nv_bfloat16 hw = __float2bfloat16(v.w);
    __nv_bfloat16 lx = __float2bfloat16(v.x - __bfloat162float(hx));
    __nv_bfloat16 ly = __float2bfloat16(v.y - __bfloat162float(hy));
    __nv_bfloat16 lz = __float2bfloat16(v.z - __bfloat162float(hz));
    __nv_bfloat16 lw = __float2bfloat16(v.w - __bfloat162float(hw));
    __nv_bfloat162 h0; h0.x = hx; h0.y = hy;
    __nv_bfloat162 h1; h1.x = hz; h1.y = hw;
    __nv_bfloat162 l0; l0.x = lx; l0.y = ly;
    __nv_bfloat162 l1; l1.x = lz; l1.y = lw;
    uint32_t uh0 = *reinterpret_cast<uint32_t*>(&h0);
    uint32_t uh1 = *reinterpret_cast<uint32_t*>(&h1);
    uint32_t ul0 = *reinterpret_cast<uint32_t*>(&l0);
    uint32_t ul1 = *reinterpret_cast<uint32_t*>(&l1);
    uint32_t off = (uint32_t)(row * 80 + col * 2);
    asm volatile("st.shared.v2.b32 [%0], {%1, %2};" :: "r"(hi_base + off), "r"(uh0), "r"(uh1) : "memory");
    asm volatile("st.shared.v2.b32 [%0], {%1, %2};" :: "r"(lo_base + off), "r"(ul0), "r"(ul1) : "memory");
}

__device__ __forceinline__ void mma16816(float* c, const uint32_t* a, const uint32_t* b)
{
    asm volatile(
        "mma.sync.aligned.m16n8k16.row.col.f32.bf16.bf16.f32 "
        "{%0,%1,%2,%3}, {%4,%5,%6,%7}, {%8,%9}, {%0,%1,%2,%3};"
        : "+f"(c[0]), "+f"(c[1]), "+f"(c[2]), "+f"(c[3])
        : "r"(a[0]), "r"(a[1]), "r"(a[2]), "r"(a[3]), "r"(b[0]), "r"(b[1]));
}

// =============== HMMA split-bf16 GEMM: C[M,N] = A[M,K] * B[N,K]^T (+bias) ===============
// BM=BN=128, BK=32, 256 threads (8 warps, 2x4), warp tile 64x32.
// Requires M%128==0, N%128==0, K%32==0, 16B-aligned rows.
__global__ void __launch_bounds__(256) k_hgemm(
    const float* __restrict__ A, int lda,
    const float* __restrict__ B, int ldb,
    const float* __restrict__ bias,
    float* __restrict__ C, int ldc, int Kd)
{
    __shared__ __align__(16) __nv_bfloat16 sm[4 * 128 * 40];   // A_hi | A_lo | B_hi | B_lo
    const int tid  = threadIdx.x;
    const int lane = tid & 31, wid = tid >> 5;
    const int wm = wid & 1, wn = wid >> 1;       // 2 x 4 warp grid
    const int bm = blockIdx.y * 128, bn = blockIdx.x * 128;

    const uint32_t sbase = smem_to_u32(sm);
    const uint32_t sA_hi = sbase;
    const uint32_t sA_lo = sbase + 128 * 80;
    const uint32_t sB_hi = sbase + 2 * 128 * 80;
    const uint32_t sB_lo = sbase + 3 * 128 * 80;

    const int lrow = tid >> 1;           // 0..127
    const int lk   = (tid & 1) * 16;     // 0 or 16

    float acc[4][4][4];
#pragma unroll
    for (int i = 0; i < 4; i++)
#pragma unroll
        for (int j = 0; j < 4; j++)
#pragma unroll
            for (int r = 0; r < 4; r++) acc[i][j][r] = 0.f;

    const int gid = lane >> 2, tid4 = lane & 3;

    const float* Aptr = A + (size_t)(bm + lrow) * lda + lk;
    const float* Bptr = B + (size_t)(bn + lrow) * ldb + lk;

    float4 ra[4], rb[4];
#pragma unroll
    for (int q = 0; q < 4; q++) {
        ra[q] = *(const float4*)(Aptr + q * 4);
        rb[q] = *(const float4*)(Bptr + q * 4);
    }

    // ldmatrix per-lane intra-tile offsets (bytes), constant across chunks
    const uint32_t aoffs = (uint32_t)((lane & 15) * 80 + (lane >> 4) * 16);          // row,(k half)
    const uint32_t boffs = (uint32_t)((lane & 7) * 80 + ((lane >> 3) & 1) * 16);     // n row,(k half)

    const int nch = Kd >> 5;
    for (int c = 0; c < nch; c++) {
        if (c) __syncthreads();
#pragma unroll
        for (int q = 0; q < 4; q++) {
            cvt_store(sA_hi, sA_lo, lrow, lk + q * 4, ra[q]);
            cvt_store(sB_hi, sB_lo, lrow, lk + q * 4, rb[q]);
        }
        if (c + 1 < nch) {
            Aptr += 32; Bptr += 32;
#pragma unroll
            for (int q = 0; q < 4; q++) {
                ra[q] = *(const float4*)(Aptr + q * 4);
                rb[q] = *(const float4*)(Bptr + q * 4);
            }
        }
        __syncthreads();

#pragma unroll
        for (int ks = 0; ks < 2; ks++) {
            const uint32_t kb = (uint32_t)(ks * 32);     // 16 bf16 = 32 bytes
            uint32_t bh[4][2], bl[4][2];
#pragma unroll
            for (int j = 0; j < 4; j++) {
                uint32_t addr = sB_hi + (uint32_t)((wn * 32 + j * 8) * 80) + boffs + kb;
                asm volatile("ldmatrix.sync.aligned.m8n8.x2.shared.b16 {%0,%1}, [%2];"
                             : "=r"(bh[j][0]), "=r"(bh[j][1]) : "r"(addr));
                addr += 128u * 80;       // sB_lo is ONE tile past sB_hi (bugfix: was 2 tiles)
                asm volatile("ldmatrix.sync.aligned.m8n8.x2.shared.b16 {%0,%1}, [%2];"
                             : "=r"(bl[j][0]), "=r"(bl[j][1]) : "r"(addr));
            }
#pragma unroll
            for (int i = 0; i < 4; i++) {
                uint32_t ah[4], al[4];
                uint32_t addr = sA_hi + (uint32_t)((wm * 64 + i * 16) * 80) + aoffs + kb;
                asm volatile("ldmatrix.sync.aligned.m8n8.x4.shared.b16 {%0,%1,%2,%3}, [%4];"
                             : "=r"(ah[0]), "=r"(ah[1]), "=r"(ah[2]), "=r"(ah[3]) : "r"(addr));
                addr += 128u * 80;       // sA_lo
                asm volatile("ldmatrix.sync.aligned.m8n8.x4.shared.b16 {%0,%1,%2,%3}, [%4];"
                             : "=r"(al[0]), "=r"(al[1]), "=r"(al[2]), "=r"(al[3]) : "r"(addr));
#pragma unroll
                for (int j = 0; j < 4; j++) {
                    mma16816(acc[i][j], ah, bh[j]);
                    mma16816(acc[i][j], ah, bl[j]);
                    mma16816(acc[i][j], al, bh[j]);
                }
            }
        }
    }

    // epilogue: fragment layout c0,c1 -> (m=gid, n=2*tid4+{0,1}); c2,c3 -> m+8
#pragma unroll
    for (int i = 0; i < 4; i++) {
        const int m0 = bm + wm * 64 + i * 16 + gid;
#pragma unroll
        for (int j = 0; j < 4; j++) {
            const int n0 = bn + wn * 32 + j * 8 + tid4 * 2;
            float bx = 0.f, by = 0.f;
            if (bias) { bx = bias[n0]; by = bias[n0 + 1]; }
            float2 v0 = { acc[i][j][0] + bx, acc[i][j][1] + by };
            float2 v1 = { acc[i][j][2] + bx, acc[i][j][3] + by };
            *(float2*)&C[(size_t)m0 * ldc + n0]       = v0;
            *(float2*)&C[(size_t)(m0 + 8) * ldc + n0] = v1;
        }
    }
}

// ---------------- embedding gather (float4) ----------------
__global__ void k_embed(const int* __restrict__ tok, const float* __restrict__ emb,
                        float* __restrict__ x)
{
    int i = blockIdx.x * blockDim.x + threadIdx.x;
    if (i >= BT * (Dd/4)) return;
    int r  = i / (Dd/4);
    int c4 = i - r * (Dd/4);
    ((float4*)x)[i] = ((const float4*)(emb + (size_t)tok[r] * Dd))[c4];
}

// ---------------- SIMT NT GEMM (kept for dt_proj, K=48) ----------------
__global__ void __launch_bounds__(256) k_gemm_nt(
    const float* __restrict__ A, int lda,
    const float* __restrict__ B, int ldb,
    const float* __restrict__ bias,
    float* __restrict__ C, int ldc, int Kd)
{
    __shared__ float As[16][128];
    __shared__ float Bs[16][128];
    const int tid = threadIdx.x;
    const int bm = blockIdx.y * 128, bn = blockIdx.x * 128;
    const int r0 = tid >> 2;
    const int kq = (tid & 3) << 2;
    const float* Ap0 = A + (size_t)(bm + r0)      * lda + kq;
    const float* Ap1 = A + (size_t)(bm + r0 + 64) * lda + kq;
    const float* Bp0 = B + (size_t)(bn + r0)      * ldb + kq;
    const float* Bp1 = B + (size_t)(bn + r0 + 64) * ldb + kq;
    const int tx = tid & 15, ty = tid >> 4;
    float acc[8][8];
#pragma unroll
    for (int i = 0; i < 8; i++)
#pragma unroll
        for (int j = 0; j < 8; j++) acc[i][j] = 0.f;
    float4 ra0 = *(const float4*)Ap0;
    float4 ra1 = *(const float4*)Ap1;
    float4 rb0 = *(const float4*)Bp0;
    float4 rb1 = *(const float4*)Bp1;
    const int ntiles = Kd >> 4;
    for (int kt = 0; kt < ntiles; kt++) {
        As[kq+0][r0]    = ra0.x; As[kq+1][r0]    = ra0.y; As[kq+2][r0]    = ra0.z; As[kq+3][r0]    = ra0.w;
        As[kq+0][r0+64] = ra1.x; As[kq+1][r0+64] = ra1.y; As[kq+2][r0+64] = ra1.z; As[kq+3][r0+64] = ra1.w;
        Bs[kq+0][r0]    = rb0.x; Bs[kq+1][r0]    = rb0.y; Bs[kq+2][r0]    = rb0.z; Bs[kq+3][r0]    = rb0.w;
        Bs[kq+0][r0+64] = rb1.x; Bs[kq+1][r0+64] = rb1.y; Bs[kq+2][r0+64] = rb1.z; Bs[kq+3][r0+64] = rb1.w;
        __syncthreads();
        if (kt + 1 < ntiles) {
            Ap0 += 16; Ap1 += 16; Bp0 += 16; Bp1 += 16;
            ra0 = *(const float4*)Ap0; ra1 = *(const float4*)Ap1;
            rb0 = *(const float4*)Bp0; rb1 = *(const float4*)Bp1;
        }
#pragma unroll
        for (int kk = 0; kk < 16; kk++) {
            float a[8], bb[8];
            *(float4*)(a)      = *(const float4*)&As[kk][ty*8];
            *(float4*)(a + 4)  = *(const float4*)&As[kk][ty*8 + 4];
            *(float4*)(bb)     = *(const float4*)&Bs[kk][tx*8];
            *(float4*)(bb + 4) = *(const float4*)&Bs[kk][tx*8 + 4];
#pragma unroll
            for (int i = 0; i < 8; i++)
#pragma unroll
                for (int j = 0; j < 8; j++)
                    acc[i][j] = fmaf(a[i], bb[j], acc[i][j]);
        }
        __syncthreads();
    }
    float bv[8];
#pragma unroll
    for (int j = 0; j < 8; j++) bv[j] = bias ? bias[bn + tx*8 + j] : 0.f;
#pragma unroll
    for (int i = 0; i < 8; i++) {
        size_t row = (size_t)(bm + ty*8 + i);
        float4 o0, o1;
        o0.x = acc[i][0] + bv[0]; o0.y = acc[i][1] + bv[1];
        o0.z = acc[i][2] + bv[2]; o0.w = acc[i][3] + bv[3];
        o1.x = acc[i][4] + bv[4]; o1.y = acc[i][5] + bv[5];
        o1.z = acc[i][6] + bv[6]; o1.w = acc[i][7] + bv[7];
        *(float4*)&C[row*ldc + bn + tx*8]     = o0;
        *(float4*)&C[row*ldc + bn + tx*8 + 4] = o1;
    }
}

// ---------------- causal depthwise conv (K=4) + bias + SiLU ----------------
__global__ void k_conv(const float* __restrict__ xz, const float* __restrict__ cw,
                       const float* __restrict__ cb, float* __restrict__ xin)
{
    int i = blockIdx.x * blockDim.x + threadIdx.x;
    if (i >= BT * EDe) return;
    int bt = i / EDe, e = i - bt * EDe;
    int b = bt >> 10, t = bt & (Tt - 1);
    float s = cb[e];
    const float* col = xz + (size_t)(b * Tt) * XZc + e;
#pragma unroll
    for (int j = 0; j < KC; j++) {
        int tt = t - (KC - 1) + j;
        if (tt >= 0) s = fmaf(cw[e*KC + j], col[(size_t)tt * XZc], s);
    }
    xin[i] = s / (1.f + __expf(-s));
}

// ---------------- pad x_proj_w (80 rows) into 128-row buffer ----------------
__global__ void k_pad(const float* __restrict__ xpw, float* __restrict__ dst)
{
    int i = blockIdx.x * blockDim.x + threadIdx.x;
    if (i >= DBCP * EDe) return;
    dst[i] = (i < (DTR + 2*NSn) * EDe) ? xpw[i] : 0.f;
}

// ---------------- delta = softplus(raw + dt_b); du = delta * xin ----------------
__global__ void k_ewdelta(const float* __restrict__ dtb)
{
    int i = blockIdx.x * blockDim.x + threadIdx.x;
    if (i >= BT * EDe) return;
    int e = i % EDe;
    float raw = g_delta[i] + dtb[e];
    float sp = (raw > 20.f) ? raw : log1pf(__expf(raw));
    g_delta[i] = sp;
    g_du[i]    = sp * g_xin[i];
}

// ---------------- selective scan: warp = 2 channels x 16 states ----------------
__global__ void k_scan(const float* __restrict__ a_log, const float* __restrict__ d_par)
{
    int gid  = blockIdx.x * blockDim.x + threadIdx.x;
    int warp = gid >> 5, lane = gid & 31;
    if (warp >= Bb * (EDe/2)) return;
    int b  = warp / (EDe/2);
    int ep = warp - b * (EDe/2);
    int e  = ep * 2 + (lane >> 4);
    int n  = lane & 15;

    float Ac = -__expf(a_log[e*NSn + n]);
    float dp = d_par[e];
    float h  = 0.f;
    size_t baseBT = (size_t)b * Tt;

    for (int t = 0; t < Tt; t++) {
        size_t bt = baseBT + t;
        float dv  = g_delta[bt*EDe + e];
        float duv = g_du   [bt*EDe + e];
        float Bv  = g_dbc  [bt*DBCP + DTR + n];
        float Cv  = g_dbc  [bt*DBCP + DTR + NSn + n];
        float dA  = __expf(dv * Ac);
        h = fmaf(dA, h, duv * Bv);
        float c = h * Cv;
        c += __shfl_xor_sync(0xffffffffu, c, 8);
        c += __shfl_xor_sync(0xffffffffu, c, 4);
        c += __shfl_xor_sync(0xffffffffu, c, 2);
        c += __shfl_xor_sync(0xffffffffu, c, 1);
        if (n == 0) {
            float xv = g_xin[bt*EDe + e];
            float zv = g_xz [bt*XZc + EDe + e];
            float gt = zv / (1.f + __expf(-zv));
            g_y[bt*EDe + e] = (c + dp * xv) * gt;
        }
    }
}

// ---------------- LayerNorm over D=768, writes into g_x ----------------
__global__ void k_ln(const float* __restrict__ w, const float* __restrict__ b)
{
    int row = blockIdx.x, tid = threadIdx.x;
    const float* r = g_out + (size_t)row * Dd;
    float v0 = r[tid], v1 = r[tid+256], v2 = r[tid+512];
    float s  = v0 + v1 + v2;
    float sq = v0*v0 + v1*v1 + v2*v2;
#pragma unroll
    for (int o = 16; o; o >>= 1) {
        s  += __shfl_xor_sync(0xffffffffu, s,  o);
        sq += __shfl_xor_sync(0xffffffffu, sq, o);
    }
    __shared__ float ss[8], sqq[8];
    if ((tid & 31) == 0) { ss[tid>>5] = s; sqq[tid>>5] = sq; }
    __syncthreads();
    s = 0.f; sq = 0.f;
#pragma unroll
    for (int i = 0; i < 8; i++) { s += ss[i]; sq += sqq[i]; }
    float mu  = s * (1.f / Dd);
    float var = sq * (1.f / Dd) - mu * mu;
    float inv = rsqrtf(var + 1e-5f);
    float* o = g_x + (size_t)row * Dd;
    o[tid]     = (v0 - mu) * inv * w[tid]     + b[tid];
    o[tid+256] = (v1 - mu) * inv * w[tid+256] + b[tid+256];
    o[tid+512] = (v2 - mu) * inv * w[tid+512] + b[tid+512];
}

// ---------------- launch ----------------
extern "C" void kernel_launch(void* const* d_in, const int* in_sizes, int n_in,
                              void* d_out, int out_size)
{
    const int*   tokens = (const int*)  d_in[0];
    const float* embed  = (const float*)d_in[1];
    const float* in_w   = (const float*)d_in[2];
    const float* conv_w = (const float*)d_in[3];
    const float* conv_b = (const float*)d_in[4];
    const float* xp_w   = (const float*)d_in[5];
    const float* dt_w   = (const float*)d_in[6];
    const float* dt_b   = (const float*)d_in[7];
    const float* a_log  = (const float*)d_in[8];
    const float* d_par  = (const float*)d_in[9];
    const float* out_w  = (const float*)d_in[10];
    const float* ln_w   = (const float*)d_in[11];
    const float* ln_b   = (const float*)d_in[12];
    const float* head_w = (const float*)d_in[13];
    const float* head_b = (const float*)d_in[14];
    float* out = (float*)d_out;

    float *p_x, *p_xz, *p_xin, *p_dbc, *p_delta, *p_y, *p_out, *p_xpw;
    cudaGetSymbolAddress((void**)&p_x,     g_x);
    cudaGetSymbolAddress((void**)&p_xz,    g_xz);
    cudaGetSymbolAddress((void**)&p_xin,   g_xin);
    cudaGetSymbolAddress((void**)&p_dbc,   g_dbc);
    cudaGetSymbolAddress((void**)&p_delta, g_delta);
    cudaGetSymbolAddress((void**)&p_y,     g_y);
    cudaGetSymbolAddress((void**)&p_out,   g_out);
    cudaGetSymbolAddress((void**)&p_xpw,   g_xpw);

    // embed
    k_embed<<<(BT*(Dd/4) + 255)/256, 256>>>(tokens, embed, p_x);

    for (int l = 0; l < NLl; l++) {
        // in_proj: xz = x @ in_w^T   (M=2048, N=3072, K=768) — HMMA split-bf16
        k_hgemm<<<dim3(XZc/128, BT/128), 256>>>(
            p_x, Dd, in_w + (size_t)l*XZc*Dd, Dd, nullptr, p_xz, XZc, Dd);

        // conv + silu
        k_conv<<<(BT*EDe + 255)/256, 256>>>(p_xz, conv_w + (size_t)l*EDe*KC,
                                            conv_b + (size_t)l*EDe, p_xin);

        // pad x_proj_w and x_proj GEMM (M=2048, N=128, K=1536) — HMMA
        k_pad<<<(DBCP*EDe + 255)/256, 256>>>(xp_w + (size_t)l*(DTR+2*NSn)*EDe, p_xpw);
        k_hgemm<<<dim3(1, BT/128), 256>>>(
            p_xin, EDe, p_xpw, EDe, nullptr, p_dbc, DBCP, EDe);

        // dt_proj GEMM (M=2048, N=1536, K=48) — SIMT (K not %32)
        k_gemm_nt<<<dim3(EDe/128, BT/128), 256>>>(
            p_dbc, DBCP, dt_w + (size_t)l*EDe*DTR, DTR, nullptr, p_delta, EDe, DTR);

        // softplus + du
        k_ewdelta<<<(BT*EDe + 255)/256, 256>>>(dt_b + (size_t)l*EDe);

        // selective scan + D skip + gate
        k_scan<<<(Bb*(EDe/2)*32 + 255)/256, 256>>>(a_log + (size_t)l*EDe*NSn,
                                                   d_par + (size_t)l*EDe);

        // out_proj GEMM (M=2048, N=768, K=1536) — HMMA
        k_hgemm<<<dim3(Dd/128, BT/128), 256>>>(
            p_y, EDe, out_w + (size_t)l*Dd*EDe, EDe, nullptr, p_out, Dd, EDe);

        // layernorm -> g_x
        k_ln<<<BT, 256>>>(ln_w + (size_t)l*Dd, ln_b + (size_t)l*Dd);
    }

    // head GEMM (M=2048, N=32000, K=768) + bias — HMMA
    k_hgemm<<<dim3(Vv/128, BT/128), 256>>>(
        p_x, Dd, head_w, Dd, head_b, out, Vv, Dd);

    (void)in_sizes; (void)n_in; (void)out_size;
}

// round 9
// speedup vs baseline: 2.3694x; 1.0091x over previous
#include <cuda_runtime.h>
#include <cuda_bf16.h>
#include <cstdint>
#include <math.h>

// ---------------- problem constants ----------------
#define Vv    32000
#define Dd    768
#define NLl   2
#define Bb    2
#define Tt    1024
#define EDe   1536
#define NSn   16
#define KC    4
#define DTR   48
#define BT    (Bb*Tt)        // 2048
#define XZc   (2*EDe)        // 3072
#define DBCP  128            // padded dbc width (80 -> 128)

// ---------------- scratch (static device globals; no allocations) ----------------
__device__ __align__(16) float g_xz   [BT*XZc];
__device__ __align__(16) float g_xin  [BT*EDe];
__device__ __align__(16) float g_dbc  [BT*DBCP];
__device__ __align__(16) float g_delta[BT*EDe];
__device__ __align__(16) float g_du   [BT*EDe];
__device__ __align__(16) float g_out  [BT*Dd];

// split bf16 activations
__device__ __align__(16) __nv_bfloat16 g_xhi  [BT*Dd];
__device__ __align__(16) __nv_bfloat16 g_xlo  [BT*Dd];
__device__ __align__(16) __nv_bfloat16 g_xinhi[BT*EDe];
__device__ __align__(16) __nv_bfloat16 g_xinlo[BT*EDe];
__device__ __align__(16) __nv_bfloat16 g_yhi  [BT*EDe];
__device__ __align__(16) __nv_bfloat16 g_ylo  [BT*EDe];

// split bf16 weights
__device__ __align__(16) __nv_bfloat16 w_inhi [NLl*XZc*Dd];
__device__ __align__(16) __nv_bfloat16 w_inlo [NLl*XZc*Dd];
__device__ __align__(16) __nv_bfloat16 w_outhi[NLl*Dd*EDe];
__device__ __align__(16) __nv_bfloat16 w_outlo[NLl*Dd*EDe];
__device__ __align__(16) __nv_bfloat16 w_hdhi [Vv*Dd];
__device__ __align__(16) __nv_bfloat16 w_hdlo [Vv*Dd];
__device__ __align__(16) __nv_bfloat16 w_xphi [NLl*DBCP*EDe];
__device__ __align__(16) __nv_bfloat16 w_xplo [NLl*DBCP*EDe];

__device__ __forceinline__ uint32_t smem_to_u32(const void* p) {
    uint32_t a;
    asm("{ .reg .u64 t; cvta.to.shared.u64 t, %1; cvt.u32.u64 %0, t; }" : "=r"(a) : "l"(p));
    return a;
}
__device__ __forceinline__ void cp16(uint32_t s, const void* g) {
    asm volatile("cp.async.cg.shared.global [%0], [%1], 16;" :: "r"(s), "l"(g));
}
#define CP_COMMIT() asm volatile("cp.async.commit_group;" ::: "memory")
#define CP_WAIT(n)  asm volatile("cp.async.wait_group %0;" :: "n"(n) : "memory")

__device__ __forceinline__ void split1(float v, __nv_bfloat16& h, __nv_bfloat16& l) {
    h = __float2bfloat16(v);
    l = __float2bfloat16(v - __bfloat162float(h));
}

__device__ __forceinline__ void mma16816(float* c, const uint32_t* a, const uint32_t* b)
{
    asm volatile(
        "mma.sync.aligned.m16n8k16.row.col.f32.bf16.bf16.f32 "
        "{%0,%1,%2,%3}, {%4,%5,%6,%7}, {%8,%9}, {%0,%1,%2,%3};"
        : "+f"(c[0]), "+f"(c[1]), "+f"(c[2]), "+f"(c[3])
        : "r"(a[0]), "r"(a[1]), "r"(a[2]), "r"(a[3]), "r"(b[0]), "r"(b[1]));
}

// ---------------- fp32 -> hi/lo bf16 split (vectorized) ----------------
__global__ void k_split(const float* __restrict__ src, __nv_bfloat16* __restrict__ hi,
                        __nv_bfloat16* __restrict__ lo, int n4)
{
    int i = blockIdx.x * blockDim.x + threadIdx.x;
    if (i >= n4) return;
    float4 v = ((const float4*)src)[i];
    __nv_bfloat16 hx, hy, hz, hw, lx, ly, lz, lw;
    split1(v.x, hx, lx); split1(v.y, hy, ly); split1(v.z, hz, lz); split1(v.w, hw, lw);
    __nv_bfloat162 h0; h0.x = hx; h0.y = hy;
    __nv_bfloat162 h1; h1.x = hz; h1.y = hw;
    __nv_bfloat162 l0; l0.x = lx; l0.y = ly;
    __nv_bfloat162 l1; l1.x = lz; l1.y = lw;
    ((__nv_bfloat162*)hi)[2*i]   = h0;  ((__nv_bfloat162*)hi)[2*i+1] = h1;
    ((__nv_bfloat162*)lo)[2*i]   = l0;  ((__nv_bfloat162*)lo)[2*i+1] = l1;
}

// ---------------- pad x_proj_w (80 rows -> 128) + split, one layer ----------------
__global__ void k_padsplit(const float* __restrict__ src, __nv_bfloat16* __restrict__ hi,
                           __nv_bfloat16* __restrict__ lo)
{
    int i = blockIdx.x * blockDim.x + threadIdx.x;
    if (i >= DBCP * EDe) return;
    float v = (i < (DTR + 2*NSn) * EDe) ? src[i] : 0.f;
    __nv_bfloat16 h, l; split1(v, h, l);
    hi[i] = h; lo[i] = l;
}

// ---------------- embedding gather -> split x ----------------
__global__ void k_embed(const int* __restrict__ tok, const float* __restrict__ emb)
{
    int i = blockIdx.x * blockDim.x + threadIdx.x;
    if (i >= BT * (Dd/4)) return;
    int r  = i / (Dd/4);
    int c4 = i - r * (Dd/4);
    float4 v = ((const float4*)(emb + (size_t)tok[r] * Dd))[c4];
    __nv_bfloat16 hx, hy, hz, hw, lx, ly, lz, lw;
    split1(v.x, hx, lx); split1(v.y, hy, ly); split1(v.z, hz, lz); split1(v.w, hw, lw);
    __nv_bfloat162 h0; h0.x = hx; h0.y = hy;
    __nv_bfloat162 h1; h1.x = hz; h1.y = hw;
    __nv_bfloat162 l0; l0.x = lx; l0.y = ly;
    __nv_bfloat162 l1; l1.x = lz; l1.y = lw;
    ((__nv_bfloat162*)g_xhi)[2*i]   = h0;  ((__nv_bfloat162*)g_xhi)[2*i+1] = h1;
    ((__nv_bfloat162*)g_xlo)[2*i]   = l0;  ((__nv_bfloat162*)g_xlo)[2*i+1] = l1;
}

// =============== pipelined HMMA split-bf16 GEMM: C = A * B^T (+bias) ===============
// Operands pre-split into hi/lo bf16 global arrays. BM=BN=128, BK=32, 256 threads,
// 8 warps (2x4), warp tile 64x32, 2-stage cp.async double buffer.
// smem per stage: 4 tiles x 128 rows x 80B = 40960 B; 2 stages = 81920 B dynamic.
#define TILE_B  10240u
#define STAGE_B 40960u
__global__ void __launch_bounds__(256) k_hgemm2(
    const __nv_bfloat16* __restrict__ Ahi, const __nv_bfloat16* __restrict__ Alo, int lda,
    const __nv_bfloat16* __restrict__ Bhi, const __nv_bfloat16* __restrict__ Blo, int ldb,
    const float* __restrict__ bias,
    float* __restrict__ C, int ldc, int Kd)
{
    extern __shared__ __align__(16) char smem[];
    const uint32_t sbase = smem_to_u32(smem);
    const int tid  = threadIdx.x;
    const int lane = tid & 31, wid = tid >> 5;
    const int wm = wid & 1, wn = wid >> 1;       // 2 x 4 warp grid
    const int bm = blockIdx.y * 128, bn = blockIdx.x * 128;

    // per-thread cp.async source/dest mapping: row = tid>>1, half = tid&1 (16 bf16)
    const int r_ld = tid >> 1;
    const int h_ld = tid & 1;
    const uint32_t so = (uint32_t)(r_ld * 80 + h_ld * 32);
    const __nv_bfloat16* gAh = Ahi + (size_t)(bm + r_ld) * lda + h_ld * 16;
    const __nv_bfloat16* gAl = Alo + (size_t)(bm + r_ld) * lda + h_ld * 16;
    const __nv_bfloat16* gBh = Bhi + (size_t)(bn + r_ld) * ldb + h_ld * 16;
    const __nv_bfloat16* gBl = Blo + (size_t)(bn + r_ld) * ldb + h_ld * 16;

    float acc[4][4][4];
#pragma unroll
    for (int i = 0; i < 4; i++)
#pragma unroll
        for (int j = 0; j < 4; j++)
#pragma unroll
            for (int r = 0; r < 4; r++) acc[i][j][r] = 0.f;

    const int gid = lane >> 2, tid4 = lane & 3;
    const uint32_t aoffs = (uint32_t)((lane & 15) * 80 + (lane >> 4) * 16);
    const uint32_t boffs = (uint32_t)((lane & 7) * 80 + ((lane >> 3) & 1) * 16);

    const int nch = Kd >> 5;

    // prefetch chunk 0 into stage 0
    {
        const uint32_t stb = sbase;
        cp16(stb + so,              gAh);  cp16(stb + so + 16,              gAh + 8);
        cp16(stb + TILE_B + so,     gAl);  cp16(stb + TILE_B + so + 16,     gAl + 8);
        cp16(stb + 2*TILE_B + so,   gBh);  cp16(stb + 2*TILE_B + so + 16,   gBh + 8);
        cp16(stb + 3*TILE_B + so,   gBl);  cp16(stb + 3*TILE_B + so + 16,   gBl + 8);
        CP_COMMIT();
    }

    for (int c = 0; c < nch; c++) {
        if (c + 1 < nch) {
            const uint32_t stb = sbase + (uint32_t)((c + 1) & 1) * STAGE_B;
            const int k = (c + 1) << 5;
            cp16(stb + so,              gAh + k);  cp16(stb + so + 16,              gAh + k + 8);
            cp16(stb + TILE_B + so,     gAl + k);  cp16(stb + TILE_B + so + 16,     gAl + k + 8);
            cp16(stb + 2*TILE_B + so,   gBh + k);  cp16(stb + 2*TILE_B + so + 16,   gBh + k + 8);
            cp16(stb + 3*TILE_B + so,   gBl + k);  cp16(stb + 3*TILE_B + so + 16,   gBl + k + 8);
            CP_COMMIT();
            CP_WAIT(1);
        } else {
            CP_WAIT(0);
        }
        __syncthreads();

        const uint32_t stb = sbase + (uint32_t)(c & 1) * STAGE_B;
#pragma unroll
        for (int ks = 0; ks < 2; ks++) {
            const uint32_t kb = (uint32_t)(ks * 32);
            uint32_t bh[4][2], bl[4][2];
#pragma unroll
            for (int j = 0; j < 4; j++) {
                uint32_t addr = stb + 2*TILE_B + (uint32_t)((wn * 32 + j * 8) * 80) + boffs + kb;
                asm volatile("ldmatrix.sync.aligned.m8n8.x2.shared.b16 {%0,%1}, [%2];"
                             : "=r"(bh[j][0]), "=r"(bh[j][1]) : "r"(addr));
                addr += TILE_B;
                asm volatile("ldmatrix.sync.aligned.m8n8.x2.shared.b16 {%0,%1}, [%2];"
                             : "=r"(bl[j][0]), "=r"(bl[j][1]) : "r"(addr));
            }
#pragma unroll
            for (int i = 0; i < 4; i++) {
                uint32_t ah[4], al[4];
                uint32_t addr = stb + (uint32_t)((wm * 64 + i * 16) * 80) + aoffs + kb;
                asm volatile("ldmatrix.sync.aligned.m8n8.x4.shared.b16 {%0,%1,%2,%3}, [%4];"
                             : "=r"(ah[0]), "=r"(ah[1]), "=r"(ah[2]), "=r"(ah[3]) : "r"(addr));
                addr += TILE_B;
                asm volatile("ldmatrix.sync.aligned.m8n8.x4.shared.b16 {%0,%1,%2,%3}, [%4];"
                             : "=r"(al[0]), "=r"(al[1]), "=r"(al[2]), "=r"(al[3]) : "r"(addr));
#pragma unroll
                for (int j = 0; j < 4; j++) {
                    mma16816(acc[i][j], ah, bh[j]);
                    mma16816(acc[i][j], ah, bl[j]);
                    mma16816(acc[i][j], al, bh[j]);
                }
            }
        }
        __syncthreads();
    }

    // epilogue
#pragma unroll
    for (int i = 0; i < 4; i++) {
        const int m0 = bm + wm * 64 + i * 16 + gid;
#pragma unroll
        for (int j = 0; j < 4; j++) {
            const int n0 = bn + wn * 32 + j * 8 + tid4 * 2;
            float bx = 0.f, by = 0.f;
            if (bias) { bx = bias[n0]; by = bias[n0 + 1]; }
            float2 v0 = { acc[i][j][0] + bx, acc[i][j][1] + by };
            float2 v1 = { acc[i][j][2] + bx, acc[i][j][3] + by };
            *(float2*)&C[(size_t)m0 * ldc + n0]       = v0;
            *(float2*)&C[(size_t)(m0 + 8) * ldc + n0] = v1;
        }
    }
}

// ---------------- SIMT NT GEMM (dt_proj, K=48) ----------------
__global__ void __launch_bounds__(256) k_gemm_nt(
    const float* __restrict__ A, int lda,
    const float* __restrict__ B, int ldb,
    float* __restrict__ C, int ldc, int Kd)
{
    __shared__ float As[16][128];
    __shared__ float Bs[16][128];
    const int tid = threadIdx.x;
    const int bm = blockIdx.y * 128, bn = blockIdx.x * 128;
    const int r0 = tid >> 2;
    const int kq = (tid & 3) << 2;
    const float* Ap0 = A + (size_t)(bm + r0)      * lda + kq;
    const float* Ap1 = A + (size_t)(bm + r0 + 64) * lda + kq;
    const float* Bp0 = B + (size_t)(bn + r0)      * ldb + kq;
    const float* Bp1 = B + (size_t)(bn + r0 + 64) * ldb + kq;
    const int tx = tid & 15, ty = tid >> 4;
    float acc[8][8];
#pragma unroll
    for (int i = 0; i < 8; i++)
#pragma unroll
        for (int j = 0; j < 8; j++) acc[i][j] = 0.f;
    float4 ra0 = *(const float4*)Ap0;
    float4 ra1 = *(const float4*)Ap1;
    float4 rb0 = *(const float4*)Bp0;
    float4 rb1 = *(const float4*)Bp1;
    const int ntiles = Kd >> 4;
    for (int kt = 0; kt < ntiles; kt++) {
        As[kq+0][r0]    = ra0.x; As[kq+1][r0]    = ra0.y; As[kq+2][r0]    = ra0.z; As[kq+3][r0]    = ra0.w;
        As[kq+0][r0+64] = ra1.x; As[kq+1][r0+64] = ra1.y; As[kq+2][r0+64] = ra1.z; As[kq+3][r0+64] = ra1.w;
        Bs[kq+0][r0]    = rb0.x; Bs[kq+1][r0]    = rb0.y; Bs[kq+2][r0]    = rb0.z; Bs[kq+3][r0]    = rb0.w;
        Bs[kq+0][r0+64] = rb1.x; Bs[kq+1][r0+64] = rb1.y; Bs[kq+2][r0+64] = rb1.z; Bs[kq+3][r0+64] = rb1.w;
        __syncthreads();
        if (kt + 1 < ntiles) {
            Ap0 += 16; Ap1 += 16; Bp0 += 16; Bp1 += 16;
            ra0 = *(const float4*)Ap0; ra1 = *(const float4*)Ap1;
            rb0 = *(const float4*)Bp0; rb1 = *(const float4*)Bp1;
        }
#pragma unroll
        for (int kk = 0; kk < 16; kk++) {
            float a[8], bb[8];
            *(float4*)(a)      = *(const float4*)&As[kk][ty*8];
            *(float4*)(a + 4)  = *(const float4*)&As[kk][ty*8 + 4];
            *(float4*)(bb)     = *(const float4*)&Bs[kk][tx*8];
            *(float4*)(bb + 4) = *(const float4*)&Bs[kk][tx*8 + 4];
#pragma unroll
            for (int i = 0; i < 8; i++)
#pragma unroll
                for (int j = 0; j < 8; j++)
                    acc[i][j] = fmaf(a[i], bb[j], acc[i][j]);
        }
        __syncthreads();
    }
#pragma unroll
    for (int i = 0; i < 8; i++) {
        size_t row = (size_t)(bm + ty*8 + i);
        float4 o0, o1;
        o0.x = acc[i][0]; o0.y = acc[i][1]; o0.z = acc[i][2]; o0.w = acc[i][3];
        o1.x = acc[i][4]; o1.y = acc[i][5]; o1.z = acc[i][6]; o1.w = acc[i][7];
        *(float4*)&C[row*ldc + bn + tx*8]     = o0;
        *(float4*)&C[row*ldc + bn + tx*8 + 4] = o1;
    }
}

// ---------------- causal depthwise conv (K=4) + bias + SiLU; writes fp32 + split ----------------
__global__ void k_conv(const float* __restrict__ xz, const float* __restrict__ cw,
                       const float* __restrict__ cb)
{
    int i = blockIdx.x * blockDim.x + threadIdx.x;
    if (i >= BT * EDe) return;
    int bt = i / EDe, e = i - bt * EDe;
    int b = bt >> 10, t = bt & (Tt - 1);
    float s = cb[e];
    const float* col = xz + (size_t)(b * Tt) * XZc + e;
#pragma unroll
    for (int j = 0; j < KC; j++) {
        int tt = t - (KC - 1) + j;
        if (tt >= 0) s = fmaf(cw[e*KC + j], col[(size_t)tt * XZc], s);
    }
    float v = s / (1.f + __expf(-s));
    g_xin[i] = v;
    __nv_bfloat16 h, l; split1(v, h, l);
    g_xinhi[i] = h; g_xinlo[i] = l;
}

// ---------------- delta = softplus(raw + dt_b); du = delta * xin ----------------
__global__ void k_ewdelta(const float* __restrict__ dtb)
{
    int i = blockIdx.x * blockDim.x + threadIdx.x;
    if (i >= BT * EDe) return;
    int e = i % EDe;
    float raw = g_delta[i] + dtb[e];
    float sp = (raw > 20.f) ? raw : log1pf(__expf(raw));
    g_delta[i] = sp;
    g_du[i]    = sp * g_xin[i];
}

// ---------------- selective scan; writes split y ----------------
__global__ void k_scan(const float* __restrict__ a_log, const float* __restrict__ d_par)
{
    int gid  = blockIdx.x * blockDim.x + threadIdx.x;
    int warp = gid >> 5, lane = gid & 31;
    if (warp >= Bb * (EDe/2)) return;
    int b  = warp / (EDe/2);
    int ep = warp - b * (EDe/2);
    int e  = ep * 2 + (lane >> 4);
    int n  = lane & 15;

    float Ac = -__expf(a_log[e*NSn + n]);
    float dp = d_par[e];
    float h  = 0.f;
    size_t baseBT = (size_t)b * Tt;

    for (int t = 0; t < Tt; t++) {
        size_t bt = baseBT + t;
        float dv  = g_delta[bt*EDe + e];
        float duv = g_du   [bt*EDe + e];
        float Bv  = g_dbc  [bt*DBCP + DTR + n];
        float Cv  = g_dbc  [bt*DBCP + DTR + NSn + n];
        float dA  = __expf(dv * Ac);
        h = fmaf(dA, h, duv * Bv);
        float c = h * Cv;
        c += __shfl_xor_sync(0xffffffffu, c, 8);
        c += __shfl_xor_sync(0xffffffffu, c, 4);
        c += __shfl_xor_sync(0xffffffffu, c, 2);
        c += __shfl_xor_sync(0xffffffffu, c, 1);
        if (n == 0) {
            float xv = g_xin[bt*EDe + e];
            float zv = g_xz [bt*XZc + EDe + e];
            float gt = zv / (1.f + __expf(-zv));
            float yv = (c + dp * xv) * gt;
            __nv_bfloat16 hh, ll; split1(yv, hh, ll);
            g_yhi[bt*EDe + e] = hh; g_ylo[bt*EDe + e] = ll;
        }
    }
}

// ---------------- LayerNorm over D=768; writes split x ----------------
__global__ void k_ln(const float* __restrict__ w, const float* __restrict__ b)
{
    int row = blockIdx.x, tid = threadIdx.x;
    const float* r = g_out + (size_t)row * Dd;
    float v0 = r[tid], v1 = r[tid+256], v2 = r[tid+512];
    float s  = v0 + v1 + v2;
    float sq = v0*v0 + v1*v1 + v2*v2;
#pragma unroll
    for (int o = 16; o; o >>= 1) {
        s  += __shfl_xor_sync(0xffffffffu, s,  o);
        sq += __shfl_xor_sync(0xffffffffu, sq, o);
    }
    __shared__ float ss[8], sqq[8];
    if ((tid & 31) == 0) { ss[tid>>5] = s; sqq[tid>>5] = sq; }
    __syncthreads();
    s = 0.f; sq = 0.f;
#pragma unroll
    for (int i = 0; i < 8; i++) { s += ss[i]; sq += sqq[i]; }
    float mu  = s * (1.f / Dd);
    float var = sq * (1.f / Dd) - mu * mu;
    float inv = rsqrtf(var + 1e-5f);
    size_t o = (size_t)row * Dd;
#pragma unroll
    for (int q = 0; q < 3; q++) {
        int c = tid + q * 256;
        float vv = (q == 0 ? v0 : (q == 1 ? v1 : v2));
        float val = (vv - mu) * inv * w[c] + b[c];
        __nv_bfloat16 hh, ll; split1(val, hh, ll);
        g_xhi[o + c] = hh; g_xlo[o + c] = ll;
    }
}

// ---------------- launch ----------------
extern "C" void kernel_launch(void* const* d_in, const int* in_sizes, int n_in,
                              void* d_out, int out_size)
{
    const int*   tokens = (const int*)  d_in[0];
    const float* embed  = (const float*)d_in[1];
    const float* in_w   = (const float*)d_in[2];
    const float* conv_w = (const float*)d_in[3];
    const float* conv_b = (const float*)d_in[4];
    const float* xp_w   = (const float*)d_in[5];
    const float* dt_w   = (const float*)d_in[6];
    const float* dt_b   = (const float*)d_in[7];
    const float* a_log  = (const float*)d_in[8];
    const float* d_par  = (const float*)d_in[9];
    const float* out_w  = (const float*)d_in[10];
    const float* ln_w   = (const float*)d_in[11];
    const float* ln_b   = (const float*)d_in[12];
    const float* head_w = (const float*)d_in[13];
    const float* head_b = (const float*)d_in[14];
    float* out = (float*)d_out;

    float *p_xz, *p_dbc, *p_delta, *p_out;
    __nv_bfloat16 *p_xhi, *p_xlo, *p_xinhi, *p_xinlo, *p_yhi, *p_ylo;
    __nv_bfloat16 *p_wih, *p_wil, *p_woh, *p_wol, *p_whh, *p_whl, *p_wxh, *p_wxl;
    cudaGetSymbolAddress((void**)&p_xz,    g_xz);
    cudaGetSymbolAddress((void**)&p_dbc,   g_dbc);
    cudaGetSymbolAddress((void**)&p_delta, g_delta);
    cudaGetSymbolAddress((void**)&p_out,   g_out);
    cudaGetSymbolAddress((void**)&p_xhi,   g_xhi);
    cudaGetSymbolAddress((void**)&p_xlo,   g_xlo);
    cudaGetSymbolAddress((void**)&p_xinhi, g_xinhi);
    cudaGetSymbolAddress((void**)&p_xinlo, g_xinlo);
    cudaGetSymbolAddress((void**)&p_yhi,   g_yhi);
    cudaGetSymbolAddress((void**)&p_ylo,   g_ylo);
    cudaGetSymbolAddress((void**)&p_wih,   w_inhi);
    cudaGetSymbolAddress((void**)&p_wil,   w_inlo);
    cudaGetSymbolAddress((void**)&p_woh,   w_outhi);
    cudaGetSymbolAddress((void**)&p_wol,   w_outlo);
    cudaGetSymbolAddress((void**)&p_whh,   w_hdhi);
    cudaGetSymbolAddress((void**)&p_whl,   w_hdlo);
    cudaGetSymbolAddress((void**)&p_wxh,   w_xphi);
    cudaGetSymbolAddress((void**)&p_wxl,   w_xplo);

    cudaFuncSetAttribute(k_hgemm2, cudaFuncAttributeMaxDynamicSharedMemorySize, 2*STAGE_B);

    // 1: split in_w (both layers)
    { int n4 = NLl*XZc*Dd/4; k_split<<<(n4+255)/256, 256>>>(in_w, p_wih, p_wil, n4); }
    // 2: embed -> split x
    k_embed<<<(BT*(Dd/4) + 255)/256, 256>>>(tokens, embed);
    // 3: split head_w
    { int n4 = Vv*Dd/4; k_split<<<(n4+255)/256, 256>>>(head_w, p_whh, p_whl, n4); }
    // 4: split out_w (both layers)
    { int n4 = NLl*Dd*EDe/4; k_split<<<(n4+255)/256, 256>>>(out_w, p_woh, p_wol, n4); }

    for (int l = 0; l < NLl; l++) {
        // in_proj (M=2048, N=3072, K=768)
        k_hgemm2<<<dim3(XZc/128, BT/128), 256, 2*STAGE_B>>>(
            p_xhi, p_xlo, Dd, p_wih + (size_t)l*XZc*Dd, p_wil + (size_t)l*XZc*Dd, Dd,
            nullptr, p_xz, XZc, Dd);

        // conv + silu -> xin fp32 + split
        k_conv<<<(BT*EDe + 255)/256, 256>>>(p_xz, conv_w + (size_t)l*EDe*KC,
                                            conv_b + (size_t)l*EDe);

        // pad+split x_proj_w; x_proj GEMM (M=2048, N=128, K=1536)
        k_padsplit<<<(DBCP*EDe + 255)/256, 256>>>(xp_w + (size_t)l*(DTR+2*NSn)*EDe,
                                                  p_wxh + (size_t)l*DBCP*EDe,
                                                  p_wxl + (size_t)l*DBCP*EDe);
        k_hgemm2<<<dim3(1, BT/128), 256, 2*STAGE_B>>>(
            p_xinhi, p_xinlo, EDe, p_wxh + (size_t)l*DBCP*EDe, p_wxl + (size_t)l*DBCP*EDe, EDe,
            nullptr, p_dbc, DBCP, EDe);

        // dt_proj GEMM (M=2048, N=1536, K=48) — SIMT
        k_gemm_nt<<<dim3(EDe/128, BT/128), 256>>>(
            p_dbc, DBCP, dt_w + (size_t)l*EDe*DTR, DTR, p_delta, EDe, DTR);

        // softplus + du
        k_ewdelta<<<(BT*EDe + 255)/256, 256>>>(dt_b + (size_t)l*EDe);

        // selective scan + D skip + gate -> split y
        k_scan<<<(Bb*(EDe/2)*32 + 255)/256, 256>>>(a_log + (size_t)l*EDe*NSn,
                                                   d_par + (size_t)l*EDe);

        // out_proj (M=2048, N=768, K=1536)
        k_hgemm2<<<dim3(Dd/128, BT/128), 256, 2*STAGE_B>>>(
            p_yhi, p_ylo, EDe, p_woh + (size_t)l*Dd*EDe, p_wol + (size_t)l*Dd*EDe, EDe,
            nullptr, p_out, Dd, EDe);

        // layernorm -> split x
        k_ln<<<BT, 256>>>(ln_w + (size_t)l*Dd, ln_b + (size_t)l*Dd);
    }

    // head GEMM (M=2048, N=32000, K=768) + bias
    k_hgemm2<<<dim3(Vv/128, BT/128), 256, 2*STAGE_B>>>(
        p_xhi, p_xlo, Dd, p_whh, p_whl, Dd, head_b, out, Vv, Dd);

    (void)in_sizes; (void)n_in; (void)out_size;
}

// round 10
// speedup vs baseline: 2.4276x; 1.0246x over previous
#include <cuda_runtime.h>
#include <cuda_bf16.h>
#include <cstdint>
#include <math.h>

// ---------------- problem constants ----------------
#define Vv    32000
#define Dd    768
#define NLl   2
#define Bb    2
#define Tt    1024
#define EDe   1536
#define NSn   16
#define KC    4
#define DTR   48
#define BT    (Bb*Tt)        // 2048
#define XZc   (2*EDe)        // 3072
#define DBCP  128            // padded dbc width (80 -> 128)

// ---------------- scratch (static device globals; no allocations) ----------------
__device__ __align__(16) float g_xz   [BT*XZc];
__device__ __align__(16) float g_xin  [BT*EDe];
__device__ __align__(16) float g_dbc  [BT*DBCP];
__device__ __align__(16) float g_delta[BT*EDe];
__device__ __align__(16) float g_du   [BT*EDe];
__device__ __align__(16) float g_out  [BT*Dd];

// split bf16 activations
__device__ __align__(16) __nv_bfloat16 g_xhi  [BT*Dd];
__device__ __align__(16) __nv_bfloat16 g_xlo  [BT*Dd];
__device__ __align__(16) __nv_bfloat16 g_xinhi[BT*EDe];
__device__ __align__(16) __nv_bfloat16 g_xinlo[BT*EDe];
__device__ __align__(16) __nv_bfloat16 g_yhi  [BT*EDe];
__device__ __align__(16) __nv_bfloat16 g_ylo  [BT*EDe];

// split bf16 weights
__device__ __align__(16) __nv_bfloat16 w_inhi [NLl*XZc*Dd];
__device__ __align__(16) __nv_bfloat16 w_inlo [NLl*XZc*Dd];
__device__ __align__(16) __nv_bfloat16 w_outhi[NLl*Dd*EDe];
__device__ __align__(16) __nv_bfloat16 w_outlo[NLl*Dd*EDe];
__device__ __align__(16) __nv_bfloat16 w_hdhi [Vv*Dd];
__device__ __align__(16) __nv_bfloat16 w_hdlo [Vv*Dd];
__device__ __align__(16) __nv_bfloat16 w_xphi [NLl*DBCP*EDe];
__device__ __align__(16) __nv_bfloat16 w_xplo [NLl*DBCP*EDe];

__device__ __forceinline__ uint32_t smem_to_u32(const void* p) {
    uint32_t a;
    asm("{ .reg .u64 t; cvta.to.shared.u64 t, %1; cvt.u32.u64 %0, t; }" : "=r"(a) : "l"(p));
    return a;
}
__device__ __forceinline__ void cp16(uint32_t s, const void* g) {
    asm volatile("cp.async.cg.shared.global [%0], [%1], 16;" :: "r"(s), "l"(g));
}
#define CP_COMMIT() asm volatile("cp.async.commit_group;" ::: "memory")
#define CP_WAIT(n)  asm volatile("cp.async.wait_group %0;" :: "n"(n) : "memory")

__device__ __forceinline__ void split1(float v, __nv_bfloat16& h, __nv_bfloat16& l) {
    h = __float2bfloat16(v);
    l = __float2bfloat16(v - __bfloat162float(h));
}

// NOTE: non-volatile — register-only effects; lets ptxas schedule/interleave HMMAs.
__device__ __forceinline__ void mma16816(float* c, const uint32_t* a, const uint32_t* b)
{
    asm("mma.sync.aligned.m16n8k16.row.col.f32.bf16.bf16.f32 "
        "{%0,%1,%2,%3}, {%4,%5,%6,%7}, {%8,%9}, {%0,%1,%2,%3};"
        : "+f"(c[0]), "+f"(c[1]), "+f"(c[2]), "+f"(c[3])
        : "r"(a[0]), "r"(a[1]), "r"(a[2]), "r"(a[3]), "r"(b[0]), "r"(b[1]));
}

// ---------------- fp32 -> hi/lo bf16 split (vectorized) ----------------
__global__ void k_split(const float* __restrict__ src, __nv_bfloat16* __restrict__ hi,
                        __nv_bfloat16* __restrict__ lo, int n4)
{
    int i = blockIdx.x * blockDim.x + threadIdx.x;
    if (i >= n4) return;
    float4 v = ((const float4*)src)[i];
    __nv_bfloat16 hx, hy, hz, hw, lx, ly, lz, lw;
    split1(v.x, hx, lx); split1(v.y, hy, ly); split1(v.z, hz, lz); split1(v.w, hw, lw);
    __nv_bfloat162 h0; h0.x = hx; h0.y = hy;
    __nv_bfloat162 h1; h1.x = hz; h1.y = hw;
    __nv_bfloat162 l0; l0.x = lx; l0.y = ly;
    __nv_bfloat162 l1; l1.x = lz; l1.y = lw;
    ((__nv_bfloat162*)hi)[2*i]   = h0;  ((__nv_bfloat162*)hi)[2*i+1] = h1;
    ((__nv_bfloat162*)lo)[2*i]   = l0;  ((__nv_bfloat162*)lo)[2*i+1] = l1;
}

// ---------------- pad x_proj_w (80 rows -> 128) + split, one layer ----------------
__global__ void k_padsplit(const float* __restrict__ src, __nv_bfloat16* __restrict__ hi,
                           __nv_bfloat16* __restrict__ lo)
{
    int i = blockIdx.x * blockDim.x + threadIdx.x;
    if (i >= DBCP * EDe) return;
    float v = (i < (DTR + 2*NSn) * EDe) ? src[i] : 0.f;
    __nv_bfloat16 h, l; split1(v, h, l);
    hi[i] = h; lo[i] = l;
}

// ---------------- embedding gather -> split x ----------------
__global__ void k_embed(const int* __restrict__ tok, const float* __restrict__ emb)
{
    int i = blockIdx.x * blockDim.x + threadIdx.x;
    if (i >= BT * (Dd/4)) return;
    int r  = i / (Dd/4);
    int c4 = i - r * (Dd/4);
    float4 v = ((const float4*)(emb + (size_t)tok[r] * Dd))[c4];
    __nv_bfloat16 hx, hy, hz, hw, lx, ly, lz, lw;
    split1(v.x, hx, lx); split1(v.y, hy, ly); split1(v.z, hz, lz); split1(v.w, hw, lw);
    __nv_bfloat162 h0; h0.x = hx; h0.y = hy;
    __nv_bfloat162 h1; h1.x = hz; h1.y = hw;
    __nv_bfloat162 l0; l0.x = lx; l0.y = ly;
    __nv_bfloat162 l1; l1.x = lz; l1.y = lw;
    ((__nv_bfloat162*)g_xhi)[2*i]   = h0;  ((__nv_bfloat162*)g_xhi)[2*i+1] = h1;
    ((__nv_bfloat162*)g_xlo)[2*i]   = l0;  ((__nv_bfloat162*)g_xlo)[2*i+1] = l1;
}

// =============== pipelined HMMA split-bf16 GEMM: C = A * B^T (+bias) ===============
// BM=BN=128, BK=32, 256 threads (8 warps, 2x4), warp tile 64x32, 2-stage cp.async.
// MMA phase restructured for ILP: all fragments hoisted, products grouped by class
// (16 independent hh, then 16 hl, then 16 lh) -> dependent-reuse distance 16.
#define TILE_B  10240u
#define STAGE_B 40960u
__global__ void __launch_bounds__(256) k_hgemm2(
    const __nv_bfloat16* __restrict__ Ahi, const __nv_bfloat16* __restrict__ Alo, int lda,
    const __nv_bfloat16* __restrict__ Bhi, const __nv_bfloat16* __restrict__ Blo, int ldb,
    const float* __restrict__ bias,
    float* __restrict__ C, int ldc, int Kd)
{
    extern __shared__ __align__(16) char smem[];
    const uint32_t sbase = smem_to_u32(smem);
    const int tid  = threadIdx.x;
    const int lane = tid & 31, wid = tid >> 5;
    const int wm = wid & 1, wn = wid >> 1;       // 2 x 4 warp grid
    const int bm = blockIdx.y * 128, bn = blockIdx.x * 128;

    const int r_ld = tid >> 1;
    const int h_ld = tid & 1;
    const uint32_t so = (uint32_t)(r_ld * 80 + h_ld * 32);
    const __nv_bfloat16* gAh = Ahi + (size_t)(bm + r_ld) * lda + h_ld * 16;
    const __nv_bfloat16* gAl = Alo + (size_t)(bm + r_ld) * lda + h_ld * 16;
    const __nv_bfloat16* gBh = Bhi + (size_t)(bn + r_ld) * ldb + h_ld * 16;
    const __nv_bfloat16* gBl = Blo + (size_t)(bn + r_ld) * ldb + h_ld * 16;

    float acc[4][4][4];
#pragma unroll
    for (int i = 0; i < 4; i++)
#pragma unroll
        for (int j = 0; j < 4; j++)
#pragma unroll
            for (int r = 0; r < 4; r++) acc[i][j][r] = 0.f;

    const int gid = lane >> 2, tid4 = lane & 3;
    const uint32_t aoffs = (uint32_t)((lane & 15) * 80 + (lane >> 4) * 16);
    const uint32_t boffs = (uint32_t)((lane & 7) * 80 + ((lane >> 3) & 1) * 16);

    const int nch = Kd >> 5;

    // prefetch chunk 0 into stage 0
    {
        const uint32_t stb = sbase;
        cp16(stb + so,              gAh);  cp16(stb + so + 16,              gAh + 8);
        cp16(stb + TILE_B + so,     gAl);  cp16(stb + TILE_B + so + 16,     gAl + 8);
        cp16(stb + 2*TILE_B + so,   gBh);  cp16(stb + 2*TILE_B + so + 16,   gBh + 8);
        cp16(stb + 3*TILE_B + so,   gBl);  cp16(stb + 3*TILE_B + so + 16,   gBl + 8);
        CP_COMMIT();
    }

    for (int c = 0; c < nch; c++) {
        if (c + 1 < nch) {
            const uint32_t stb = sbase + (uint32_t)((c + 1) & 1) * STAGE_B;
            const int k = (c + 1) << 5;
            cp16(stb + so,              gAh + k);  cp16(stb + so + 16,              gAh + k + 8);
            cp16(stb + TILE_B + so,     gAl + k);  cp16(stb + TILE_B + so + 16,     gAl + k + 8);
            cp16(stb + 2*TILE_B + so,   gBh + k);  cp16(stb + 2*TILE_B + so + 16,   gBh + k + 8);
            cp16(stb + 3*TILE_B + so,   gBl + k);  cp16(stb + 3*TILE_B + so + 16,   gBl + k + 8);
            CP_COMMIT();
            CP_WAIT(1);
        } else {
            CP_WAIT(0);
        }
        __syncthreads();

        const uint32_t stb = sbase + (uint32_t)(c & 1) * STAGE_B;
#pragma unroll
        for (int ks = 0; ks < 2; ks++) {
            const uint32_t kb = (uint32_t)(ks * 32);
            uint32_t bh[4][2], bl[4][2], ah[4][4], al[4][4];
#pragma unroll
            for (int j = 0; j < 4; j++) {
                uint32_t addr = stb + 2*TILE_B + (uint32_t)((wn * 32 + j * 8) * 80) + boffs + kb;
                asm volatile("ldmatrix.sync.aligned.m8n8.x2.shared.b16 {%0,%1}, [%2];"
                             : "=r"(bh[j][0]), "=r"(bh[j][1]) : "r"(addr));
                addr += TILE_B;
                asm volatile("ldmatrix.sync.aligned.m8n8.x2.shared.b16 {%0,%1}, [%2];"
                             : "=r"(bl[j][0]), "=r"(bl[j][1]) : "r"(addr));
            }
#pragma unroll
            for (int i = 0; i < 4; i++) {
                uint32_t addr = stb + (uint32_t)((wm * 64 + i * 16) * 80) + aoffs + kb;
                asm volatile("ldmatrix.sync.aligned.m8n8.x4.shared.b16 {%0,%1,%2,%3}, [%4];"
                             : "=r"(ah[i][0]), "=r"(ah[i][1]), "=r"(ah[i][2]), "=r"(ah[i][3]) : "r"(addr));
                addr += TILE_B;
                asm volatile("ldmatrix.sync.aligned.m8n8.x4.shared.b16 {%0,%1,%2,%3}, [%4];"
                             : "=r"(al[i][0]), "=r"(al[i][1]), "=r"(al[i][2]), "=r"(al[i][3]) : "r"(addr));
            }
            // 16 independent hh products
#pragma unroll
            for (int i = 0; i < 4; i++)
#pragma unroll
                for (int j = 0; j < 4; j++) mma16816(acc[i][j], ah[i], bh[j]);
            // 16 hl products (reuse distance 16 from hh)
#pragma unroll
            for (int i = 0; i < 4; i++)
#pragma unroll
                for (int j = 0; j < 4; j++) mma16816(acc[i][j], ah[i], bl[j]);
            // 16 lh products
#pragma unroll
            for (int i = 0; i < 4; i++)
#pragma unroll
                for (int j = 0; j < 4; j++) mma16816(acc[i][j], al[i], bh[j]);
        }
        __syncthreads();
    }

    // epilogue
#pragma unroll
    for (int i = 0; i < 4; i++) {
        const int m0 = bm + wm * 64 + i * 16 + gid;
#pragma unroll
        for (int j = 0; j < 4; j++) {
            const int n0 = bn + wn * 32 + j * 8 + tid4 * 2;
            float bx = 0.f, by = 0.f;
            if (bias) { bx = bias[n0]; by = bias[n0 + 1]; }
            float2 v0 = { acc[i][j][0] + bx, acc[i][j][1] + by };
            float2 v1 = { acc[i][j][2] + bx, acc[i][j][3] + by };
            *(float2*)&C[(size_t)m0 * ldc + n0]       = v0;
            *(float2*)&C[(size_t)(m0 + 8) * ldc + n0] = v1;
        }
    }
}

// ---------------- SIMT NT GEMM (dt_proj, K=48) ----------------
__global__ void __launch_bounds__(256) k_gemm_nt(
    const float* __restrict__ A, int lda,
    const float* __restrict__ B, int ldb,
    float* __restrict__ C, int ldc, int Kd)
{
    __shared__ float As[16][128];
    __shared__ float Bs[16][128];
    const int tid = threadIdx.x;
    const int bm = blockIdx.y * 128, bn = blockIdx.x * 128;
    const int r0 = tid >> 2;
    const int kq = (tid & 3) << 2;
    const float* Ap0 = A + (size_t)(bm + r0)      * lda + kq;
    const float* Ap1 = A + (size_t)(bm + r0 + 64) * lda + kq;
    const float* Bp0 = B + (size_t)(bn + r0)      * ldb + kq;
    const float* Bp1 = B + (size_t)(bn + r0 + 64) * ldb + kq;
    const int tx = tid & 15, ty = tid >> 4;
    float acc[8][8];
#pragma unroll
    for (int i = 0; i < 8; i++)
#pragma unroll
        for (int j = 0; j < 8; j++) acc[i][j] = 0.f;
    float4 ra0 = *(const float4*)Ap0;
    float4 ra1 = *(const float4*)Ap1;
    float4 rb0 = *(const float4*)Bp0;
    float4 rb1 = *(const float4*)Bp1;
    const int ntiles = Kd >> 4;
    for (int kt = 0; kt < ntiles; kt++) {
        As[kq+0][r0]    = ra0.x; As[kq+1][r0]    = ra0.y; As[kq+2][r0]    = ra0.z; As[kq+3][r0]    = ra0.w;
        As[kq+0][r0+64] = ra1.x; As[kq+1][r0+64] = ra1.y; As[kq+2][r0+64] = ra1.z; As[kq+3][r0+64] = ra1.w;
        Bs[kq+0][r0]    = rb0.x; Bs[kq+1][r0]    = rb0.y; Bs[kq+2][r0]    = rb0.z; Bs[kq+3][r0]    = rb0.w;
        Bs[kq+0][r0+64] = rb1.x; Bs[kq+1][r0+64] = rb1.y; Bs[kq+2][r0+64] = rb1.z; Bs[kq+3][r0+64] = rb1.w;
        __syncthreads();
        if (kt + 1 < ntiles) {
            Ap0 += 16; Ap1 += 16; Bp0 += 16; Bp1 += 16;
            ra0 = *(const float4*)Ap0; ra1 = *(const float4*)Ap1;
            rb0 = *(const float4*)Bp0; rb1 = *(const float4*)Bp1;
        }
#pragma unroll
        for (int kk = 0; kk < 16; kk++) {
            float a[8], bb[8];
            *(float4*)(a)      = *(const float4*)&As[kk][ty*8];
            *(float4*)(a + 4)  = *(const float4*)&As[kk][ty*8 + 4];
            *(float4*)(bb)     = *(const float4*)&Bs[kk][tx*8];
            *(float4*)(bb + 4) = *(const float4*)&Bs[kk][tx*8 + 4];
#pragma unroll
            for (int i = 0; i < 8; i++)
#pragma unroll
                for (int j = 0; j < 8; j++)
                    acc[i][j] = fmaf(a[i], bb[j], acc[i][j]);
        }
        __syncthreads();
    }
#pragma unroll
    for (int i = 0; i < 8; i++) {
        size_t row = (size_t)(bm + ty*8 + i);
        float4 o0, o1;
        o0.x = acc[i][0]; o0.y = acc[i][1]; o0.z = acc[i][2]; o0.w = acc[i][3];
        o1.x = acc[i][4]; o1.y = acc[i][5]; o1.z = acc[i][6]; o1.w = acc[i][7];
        *(float4*)&C[row*ldc + bn + tx*8]     = o0;
        *(float4*)&C[row*ldc + bn + tx*8 + 4] = o1;
    }
}

// ---------------- causal depthwise conv (K=4) + bias + SiLU; writes fp32 + split ----------------
__global__ void k_conv(const float* __restrict__ xz, const float* __restrict__ cw,
                       const float* __restrict__ cb)
{
    int i = blockIdx.x * blockDim.x + threadIdx.x;
    if (i >= BT * EDe) return;
    int bt = i / EDe, e = i - bt * EDe;
    int b = bt >> 10, t = bt & (Tt - 1);
    float s = cb[e];
    const float* col = xz + (size_t)(b * Tt) * XZc + e;
#pragma unroll
    for (int j = 0; j < KC; j++) {
        int tt = t - (KC - 1) + j;
        if (tt >= 0) s = fmaf(cw[e*KC + j], col[(size_t)tt * XZc], s);
    }
    float v = s / (1.f + __expf(-s));
    g_xin[i] = v;
    __nv_bfloat16 h, l; split1(v, h, l);
    g_xinhi[i] = h; g_xinlo[i] = l;
}

// ---------------- delta = softplus(raw + dt_b); du = delta * xin ----------------
__global__ void k_ewdelta(const float* __restrict__ dtb)
{
    int i = blockIdx.x * blockDim.x + threadIdx.x;
    if (i >= BT * EDe) return;
    int e = i % EDe;
    float raw = g_delta[i] + dtb[e];
    float sp = (raw > 20.f) ? raw : log1pf(__expf(raw));
    g_delta[i] = sp;
    g_du[i]    = sp * g_xin[i];
}

// ---------------- selective scan; writes split y ----------------
__global__ void k_scan(const float* __restrict__ a_log, const float* __restrict__ d_par)
{
    int gid  = blockIdx.x * blockDim.x + threadIdx.x;
    int warp = gid >> 5, lane = gid & 31;
    if (warp >= Bb * (EDe/2)) return;
    int b  = warp / (EDe/2);
    int ep = warp - b * (EDe/2);
    int e  = ep * 2 + (lane >> 4);
    int n  = lane & 15;

    float Ac = -__expf(a_log[e*NSn + n]);
    float dp = d_par[e];
    float h  = 0.f;
    size_t baseBT = (size_t)b * Tt;

    for (int t = 0; t < Tt; t++) {
        size_t bt = baseBT + t;
        float dv  = g_delta[bt*EDe + e];
        float duv = g_du   [bt*EDe + e];
        float Bv  = g_dbc  [bt*DBCP + DTR + n];
        float Cv  = g_dbc  [bt*DBCP + DTR + NSn + n];
        float dA  = __expf(dv * Ac);
        h = fmaf(dA, h, duv * Bv);
        float c = h * Cv;
        c += __shfl_xor_sync(0xffffffffu, c, 8);
        c += __shfl_xor_sync(0xffffffffu, c, 4);
        c += __shfl_xor_sync(0xffffffffu, c, 2);
        c += __shfl_xor_sync(0xffffffffu, c, 1);
        if (n == 0) {
            float xv = g_xin[bt*EDe + e];
            float zv = g_xz [bt*XZc + EDe + e];
            float gt = zv / (1.f + __expf(-zv));
            float yv = (c + dp * xv) * gt;
            __nv_bfloat16 hh, ll; split1(yv, hh, ll);
            g_yhi[bt*EDe + e] = hh; g_ylo[bt*EDe + e] = ll;
        }
    }
}

// ---------------- LayerNorm over D=768; writes split x ----------------
__global__ void k_ln(const float* __restrict__ w, const float* __restrict__ b)
{
    int row = blockIdx.x, tid = threadIdx.x;
    const float* r = g_out + (size_t)row * Dd;
    float v0 = r[tid], v1 = r[tid+256], v2 = r[tid+512];
    float s  = v0 + v1 + v2;
    float sq = v0*v0 + v1*v1 + v2*v2;
#pragma unroll
    for (int o = 16; o; o >>= 1) {
        s  += __shfl_xor_sync(0xffffffffu, s,  o);
        sq += __shfl_xor_sync(0xffffffffu, sq, o);
    }
    __shared__ float ss[8], sqq[8];
    if ((tid & 31) == 0) { ss[tid>>5] = s; sqq[tid>>5] = sq; }
    __syncthreads();
    s = 0.f; sq = 0.f;
#pragma unroll
    for (int i = 0; i < 8; i++) { s += ss[i]; sq += sqq[i]; }
    float mu  = s * (1.f / Dd);
    float var = sq * (1.f / Dd) - mu * mu;
    float inv = rsqrtf(var + 1e-5f);
    size_t o = (size_t)row * Dd;
#pragma unroll
    for (int q = 0; q < 3; q++) {
        int c = tid + q * 256;
        float vv = (q == 0 ? v0 : (q == 1 ? v1 : v2));
        float val = (vv - mu) * inv * w[c] + b[c];
        __nv_bfloat16 hh, ll; split1(val, hh, ll);
        g_xhi[o + c] = hh; g_xlo[o + c] = ll;
    }
}

// ---------------- launch ----------------
extern "C" void kernel_launch(void* const* d_in, const int* in_sizes, int n_in,
                              void* d_out, int out_size)
{
    const int*   tokens = (const int*)  d_in[0];
    const float* embed  = (const float*)d_in[1];
    const float* in_w   = (const float*)d_in[2];
    const float* conv_w = (const float*)d_in[3];
    const float* conv_b = (const float*)d_in[4];
    const float* xp_w   = (const float*)d_in[5];
    const float* dt_w   = (const float*)d_in[6];
    const float* dt_b   = (const float*)d_in[7];
    const float* a_log  = (const float*)d_in[8];
    const float* d_par  = (const float*)d_in[9];
    const float* out_w  = (const float*)d_in[10];
    const float* ln_w   = (const float*)d_in[11];
    const float* ln_b   = (const float*)d_in[12];
    const float* head_w = (const float*)d_in[13];
    const float* head_b = (const float*)d_in[14];
    float* out = (float*)d_out;

    float *p_xz, *p_dbc, *p_delta, *p_out;
    __nv_bfloat16 *p_xhi, *p_xlo, *p_xinhi, *p_xinlo, *p_yhi, *p_ylo;
    __nv_bfloat16 *p_wih, *p_wil, *p_woh, *p_wol, *p_whh, *p_whl, *p_wxh, *p_wxl;
    cudaGetSymbolAddress((void**)&p_xz,    g_xz);
    cudaGetSymbolAddress((void**)&p_dbc,   g_dbc);
    cudaGetSymbolAddress((void**)&p_delta, g_delta);
    cudaGetSymbolAddress((void**)&p_out,   g_out);
    cudaGetSymbolAddress((void**)&p_xhi,   g_xhi);
    cudaGetSymbolAddress((void**)&p_xlo,   g_xlo);
    cudaGetSymbolAddress((void**)&p_xinhi, g_xinhi);
    cudaGetSymbolAddress((void**)&p_xinlo, g_xinlo);
    cudaGetSymbolAddress((void**)&p_yhi,   g_yhi);
    cudaGetSymbolAddress((void**)&p_ylo,   g_ylo);
    cudaGetSymbolAddress((void**)&p_wih,   w_inhi);
    cudaGetSymbolAddress((void**)&p_wil,   w_inlo);
    cudaGetSymbolAddress((void**)&p_woh,   w_outhi);
    cudaGetSymbolAddress((void**)&p_wol,   w_outlo);
    cudaGetSymbolAddress((void**)&p_whh,   w_hdhi);
    cudaGetSymbolAddress((void**)&p_whl,   w_hdlo);
    cudaGetSymbolAddress((void**)&p_wxh,   w_xphi);
    cudaGetSymbolAddress((void**)&p_wxl,   w_xplo);

    cudaFuncSetAttribute(k_hgemm2, cudaFuncAttributeMaxDynamicSharedMemorySize, 2*STAGE_B);

    // weight/activation splits
    { int n4 = NLl*XZc*Dd/4; k_split<<<(n4+255)/256, 256>>>(in_w, p_wih, p_wil, n4); }
    k_embed<<<(BT*(Dd/4) + 255)/256, 256>>>(tokens, embed);
    { int n4 = Vv*Dd/4; k_split<<<(n4+255)/256, 256>>>(head_w, p_whh, p_whl, n4); }
    { int n4 = NLl*Dd*EDe/4; k_split<<<(n4+255)/256, 256>>>(out_w, p_woh, p_wol, n4); }

    for (int l = 0; l < NLl; l++) {
        // in_proj (M=2048, N=3072, K=768)
        k_hgemm2<<<dim3(XZc/128, BT/128), 256, 2*STAGE_B>>>(
            p_xhi, p_xlo, Dd, p_wih + (size_t)l*XZc*Dd, p_wil + (size_t)l*XZc*Dd, Dd,
            nullptr, p_xz, XZc, Dd);

        // conv + silu -> xin fp32 + split
        k_conv<<<(BT*EDe + 255)/256, 256>>>(p_xz, conv_w + (size_t)l*EDe*KC,
                                            conv_b + (size_t)l*EDe);

        // pad+split x_proj_w; x_proj GEMM (M=2048, N=128, K=1536)
        k_padsplit<<<(DBCP*EDe + 255)/256, 256>>>(xp_w + (size_t)l*(DTR+2*NSn)*EDe,
                                                  p_wxh + (size_t)l*DBCP*EDe,
                                                  p_wxl + (size_t)l*DBCP*EDe);
        k_hgemm2<<<dim3(1, BT/128), 256, 2*STAGE_B>>>(
            p_xinhi, p_xinlo, EDe, p_wxh + (size_t)l*DBCP*EDe, p_wxl + (size_t)l*DBCP*EDe, EDe,
            nullptr, p_dbc, DBCP, EDe);

        // dt_proj GEMM (M=2048, N=1536, K=48) — SIMT
        k_gemm_nt<<<dim3(EDe/128, BT/128), 256>>>(
            p_dbc, DBCP, dt_w + (size_t)l*EDe*DTR, DTR, p_delta, EDe, DTR);

        // softplus + du
        k_ewdelta<<<(BT*EDe + 255)/256, 256>>>(dt_b + (size_t)l*EDe);

        // selective scan + D skip + gate -> split y
        k_scan<<<(Bb*(EDe/2)*32 + 255)/256, 256>>>(a_log + (size_t)l*EDe*NSn,
                                                   d_par + (size_t)l*EDe);

        // out_proj (M=2048, N=768, K=1536)
        k_hgemm2<<<dim3(Dd/128, BT/128), 256, 2*STAGE_B>>>(
            p_yhi, p_ylo, EDe, p_woh + (size_t)l*Dd*EDe, p_wol + (size_t)l*Dd*EDe, EDe,
            nullptr, p_out, Dd, EDe);

        // layernorm -> split x
        k_ln<<<BT, 256>>>(ln_w + (size_t)l*Dd, ln_b + (size_t)l*Dd);
    }

    // head GEMM (M=2048, N=32000, K=768) + bias
    k_hgemm2<<<dim3(Vv/128, BT/128), 256, 2*STAGE_B>>>(
        p_xhi, p_xlo, Dd, p_whh, p_whl, Dd, head_b, out, Vv, Dd);

    (void)in_sizes; (void)n_in; (void)out_size;
}